// round 2
// baseline (speedup 1.0000x reference)
#include <cuda_runtime.h>
#include <cuda_bf16.h>

#define BATCH 4
#define SEQ   4096
#define EMB   1024
#define HD    64
#define NSEG  8
#define CH    512   // keys per split-K segment

// Scratch (static device allocations are the sanctioned workaround)
__device__ float g_Q[BATCH * SEQ * HD];
__device__ float g_K[BATCH * SEQ * HD];
__device__ float g_V[BATCH * SEQ * HD];
__device__ float g_pO[BATCH * NSEG * SEQ * HD];  // partial outputs (32 MB)
__device__ float g_pL[BATCH * NSEG * SEQ];       // partial softmax denominators

// ---------------------------------------------------------------------------
// Fast exp on the FMA/ALU pipes (avoids MUFU bottleneck: we need ~34M exps).
// exp(s) = 2^(s*log2e); |s| <= ~10 here so no overflow handling needed.
// ---------------------------------------------------------------------------
__device__ __forceinline__ float fexp(float s) {
    float y = s * 1.4426950408889634f;
    float r = rintf(y);
    float f = y - r;
    float z = 0.0013333558f;
    z = z * f + 0.0096181291f;
    z = z * f + 0.0555041087f;
    z = z * f + 0.2402265070f;
    z = z * f + 0.6931471806f;
    z = z * f + 1.0f;
    int e = (int)r;
    float sc = __int_as_float((e + 127) << 23);
    return z * sc;
}

// ---------------------------------------------------------------------------
// QKV projection: Out[m][d] = sum_e x[m][e] * W[d][e],  m in [0, B*S)
// BM=128, BN=64 (full head dim), BK=32, 256 threads, 8x4 microtile/thread.
// Q is pre-scaled by 1/sqrt(64).
// ---------------------------------------------------------------------------
__global__ __launch_bounds__(256) void qkv_kernel(
    const float* __restrict__ x,
    const float* __restrict__ Wq,
    const float* __restrict__ Wk,
    const float* __restrict__ Wv)
{
    const int BM = 128, BK = 32, SX = BM + 4, SW = HD + 4;
    __shared__ float xs[BK][SX];  // stride 132 floats = 528B (16B aligned)
    __shared__ float ws[BK][SW];  // stride 68 floats  = 272B (16B aligned)

    int which = blockIdx.y;
    const float* W = (which == 0) ? Wq : ((which == 1) ? Wk : Wv);
    float* Out = (which == 0) ? g_Q : ((which == 1) ? g_K : g_V);

    int m0 = blockIdx.x * BM;
    int tid = threadIdx.x;
    int tx = tid & 15;   // 16 col groups of 4
    int ty = tid >> 4;   // 16 row groups of 8

    float acc[8][4];
#pragma unroll
    for (int i = 0; i < 8; i++)
#pragma unroll
        for (int j = 0; j < 4; j++) acc[i][j] = 0.f;

    for (int k0 = 0; k0 < EMB; k0 += BK) {
#pragma unroll
        for (int i = 0; i < 4; i++) {           // x tile: 128x32
            int lin = tid + i * 256;            // 0..1023 (float4 units)
            int row = lin & 127;
            int c4  = lin >> 7;                 // 0..7
            float4 v = *(const float4*)&x[(size_t)(m0 + row) * EMB + k0 + c4 * 4];
            xs[c4 * 4 + 0][row] = v.x; xs[c4 * 4 + 1][row] = v.y;
            xs[c4 * 4 + 2][row] = v.z; xs[c4 * 4 + 3][row] = v.w;
        }
#pragma unroll
        for (int i = 0; i < 2; i++) {           // W tile: 64x32
            int lin = tid + i * 256;            // 0..511
            int d  = lin & 63;
            int c4 = lin >> 6;                  // 0..7
            float4 v = *(const float4*)&W[(size_t)d * EMB + k0 + c4 * 4];
            ws[c4 * 4 + 0][d] = v.x; ws[c4 * 4 + 1][d] = v.y;
            ws[c4 * 4 + 2][d] = v.z; ws[c4 * 4 + 3][d] = v.w;
        }
        __syncthreads();
#pragma unroll
        for (int kk = 0; kk < BK; kk++) {
            float a[8], b[4];
            *(float4*)&a[0] = *(const float4*)&xs[kk][ty * 8];
            *(float4*)&a[4] = *(const float4*)&xs[kk][ty * 8 + 4];
            *(float4*)&b[0] = *(const float4*)&ws[kk][tx * 4];
#pragma unroll
            for (int i = 0; i < 8; i++)
#pragma unroll
                for (int j = 0; j < 4; j++) acc[i][j] += a[i] * b[j];
        }
        __syncthreads();
    }

    float scale = (which == 0) ? 0.125f : 1.0f;   // 1/sqrt(64) folded into Q
#pragma unroll
    for (int i = 0; i < 8; i++) {
        int m = m0 + ty * 8 + i;
        float4 v = make_float4(acc[i][0] * scale, acc[i][1] * scale,
                               acc[i][2] * scale, acc[i][3] * scale);
        *(float4*)&Out[(size_t)m * HD + tx * 4] = v;
    }
}

// ---------------------------------------------------------------------------
// Split-K flash attention (no-running-max softmax; partials sum linearly).
// Block = 128 threads = 128 query rows (row per thread, q & o in registers).
// Each block handles one (batch, q-tile of 128 rows, key segment of 512).
// Blocks whose segment lies entirely above the diagonal exit immediately.
// ---------------------------------------------------------------------------
__global__ __launch_bounds__(128) void attn_kernel()
{
    const int SKS = HD + 4;                 // 68-float stride, 16B aligned rows
    __shared__ float ks[32][SKS];
    __shared__ float vs[32][SKS];

    int qt  = blockIdx.x;                   // 0..31
    int b   = blockIdx.y;                   // 0..3
    int seg = blockIdx.z;                   // 0..7
    int tid = threadIdx.x;
    int row = qt * 128 + tid;

    int k0 = seg * CH;
    int rowmax = qt * 128 + 127;
    if (k0 > rowmax) return;                // segment fully above diagonal
    int klast = min(k0 + CH - 1, rowmax);
    int nt = ((klast - k0) >> 5) + 1;       // 32-key tiles in this segment

    const float* qrow = &g_Q[((size_t)b * SEQ + row) * HD];
    const float* Kb = &g_K[(size_t)b * SEQ * HD];
    const float* Vb = &g_V[(size_t)b * SEQ * HD];

    float q[HD], o[HD];
#pragma unroll
    for (int d = 0; d < HD; d += 4) {
        float4 v = *(const float4*)&qrow[d];
        q[d] = v.x; q[d + 1] = v.y; q[d + 2] = v.z; q[d + 3] = v.w;
        o[d] = 0.f; o[d + 1] = 0.f; o[d + 2] = 0.f; o[d + 3] = 0.f;
    }
    float l = 0.f;

    // loader mapping: 4 lanes per key row -> fully coalesced 256B per row
    int lrow = tid >> 2;                    // 0..31
    int loff = (tid & 3) * 16;              // 0,16,32,48

    for (int t32 = 0; t32 < nt; t32++) {
        int kb = k0 + t32 * 32;
        {
            const float* kr = &Kb[(size_t)(kb + lrow) * HD + loff];
            const float* vr = &Vb[(size_t)(kb + lrow) * HD + loff];
#pragma unroll
            for (int i = 0; i < 4; i++) {
                *(float4*)&ks[lrow][loff + i * 4] = *(const float4*)&kr[i * 4];
                *(float4*)&vs[lrow][loff + i * 4] = *(const float4*)&vr[i * 4];
            }
        }
        __syncthreads();

#pragma unroll 2
        for (int j = 0; j < 32; j++) {
            float s0 = 0.f, s1 = 0.f, s2 = 0.f, s3 = 0.f;
#pragma unroll
            for (int d = 0; d < HD; d += 4) {
                s0 += q[d]     * ks[j][d];
                s1 += q[d + 1] * ks[j][d + 1];
                s2 += q[d + 2] * ks[j][d + 2];
                s3 += q[d + 3] * ks[j][d + 3];
            }
            float s = (s0 + s1) + (s2 + s3);
            float pj = fexp(s);
            if (kb + j > row) pj = 0.f;     // causal mask
            l += pj;
#pragma unroll
            for (int d = 0; d < HD; d++) o[d] += pj * vs[j][d];
        }
        __syncthreads();
    }

    // store partial (o, l); rows with no valid keys in this segment are
    // simply never read back by the reduce kernel.
    float* po = &g_pO[(((size_t)b * NSEG + seg) * SEQ + row) * HD];
#pragma unroll
    for (int d = 0; d < HD; d += 4) {
        float4 v = make_float4(o[d], o[d + 1], o[d + 2], o[d + 3]);
        *(float4*)&po[d] = v;
    }
    g_pL[((size_t)b * NSEG + seg) * SEQ + row] = l;
}

// ---------------------------------------------------------------------------
// Reduce: out[b][row][d] = sum_s pO / sum_s pL over valid segments only.
// ---------------------------------------------------------------------------
__global__ __launch_bounds__(256) void reduce_kernel(float* __restrict__ out)
{
    int idx = blockIdx.x * 256 + threadIdx.x;
    if (idx >= BATCH * SEQ * HD) return;
    int d   = idx & (HD - 1);
    int row = (idx >> 6) & (SEQ - 1);
    int b   = idx >> 18;
    int ns  = (row / CH) + 1;               // number of valid segments

    float so = 0.f, sl = 0.f;
    for (int s = 0; s < ns; s++) {
        so += g_pO[(((size_t)b * NSEG + s) * SEQ + row) * HD + d];
        sl += g_pL[((size_t)b * NSEG + s) * SEQ + row];
    }
    out[idx] = so / sl;
}

// ---------------------------------------------------------------------------
extern "C" void kernel_launch(void* const* d_in, const int* in_sizes, int n_in,
                              void* d_out, int out_size)
{
    const float* x  = (const float*)d_in[0];
    const float* Wq = (const float*)d_in[1];
    const float* Wk = (const float*)d_in[2];
    const float* Wv = (const float*)d_in[3];
    float* out = (float*)d_out;

    qkv_kernel<<<dim3(BATCH * SEQ / 128, 3), 256>>>(x, Wq, Wk, Wv);
    attn_kernel<<<dim3(SEQ / 128, BATCH, NSEG), 128>>>();
    reduce_kernel<<<(BATCH * SEQ * HD + 255) / 256, 256>>>(out);
}

// round 3
// speedup vs baseline: 3.8207x; 3.8207x over previous
#include <cuda_runtime.h>
#include <cuda_fp16.h>
#include <cstdint>

#define BATCH 4
#define SEQ   4096
#define EMB   1024
#define HD    64
#define NSEG  4
#define CH    1024

__device__ float  g_Q[BATCH * SEQ * HD];      // tf32-rounded, pre-scaled 0.125*log2e
__device__ float  g_K[BATCH * SEQ * HD];      // tf32-rounded
__device__ __half g_Vh[BATCH * HD * SEQ];     // V transposed [b][d][s], fp16
__device__ float  g_pO[BATCH * NSEG * SEQ * HD];
__device__ float  g_pL[BATCH * NSEG * SEQ];

__device__ __forceinline__ float cvt_tf32(float x) {
    uint32_t r; asm("cvt.rna.tf32.f32 %0, %1;" : "=r"(r) : "f"(x));
    return __uint_as_float(r);
}
__device__ __forceinline__ float ex2(float x) {
    float r; asm("ex2.approx.f32 %0, %1;" : "=f"(r) : "f"(x)); return r;
}
__device__ __forceinline__ void mma_tf32(float (&c)[4], const float (&a)[4], float b0, float b1) {
    asm volatile(
        "mma.sync.aligned.m16n8k8.row.col.f32.tf32.tf32.f32 "
        "{%0,%1,%2,%3}, {%4,%5,%6,%7}, {%8,%9}, {%0,%1,%2,%3};"
        : "+f"(c[0]), "+f"(c[1]), "+f"(c[2]), "+f"(c[3])
        : "r"(__float_as_uint(a[0])), "r"(__float_as_uint(a[1])),
          "r"(__float_as_uint(a[2])), "r"(__float_as_uint(a[3])),
          "r"(__float_as_uint(b0)), "r"(__float_as_uint(b1)));
}
__device__ __forceinline__ void mma_f16(float (&c)[4], uint32_t a0, uint32_t a1,
                                        uint32_t a2, uint32_t a3, uint32_t b0, uint32_t b1) {
    asm volatile(
        "mma.sync.aligned.m16n8k16.row.col.f32.f16.f16.f32 "
        "{%0,%1,%2,%3}, {%4,%5,%6,%7}, {%8,%9}, {%0,%1,%2,%3};"
        : "+f"(c[0]), "+f"(c[1]), "+f"(c[2]), "+f"(c[3])
        : "r"(a0), "r"(a1), "r"(a2), "r"(a3), "r"(b0), "r"(b1));
}

// ---------------------------------------------------------------------------
// QKV: Out[m][d] = sum_e x[m][e]*W[d][e].  BM=128 BN=64 BK=32, 256 thr,
// 8 warps = 4m x 2n.  which: 0=Q(scaled,tf32) 1=K(tf32) 2=V(fp16, transposed).
// ---------------------------------------------------------------------------
__global__ __launch_bounds__(256) void qkv_kernel(
    const float* __restrict__ x, const float* __restrict__ Wq,
    const float* __restrict__ Wk, const float* __restrict__ Wv)
{
    __shared__ __align__(16) float xs[128 * 36];
    __shared__ __align__(16) float ws[64 * 36];

    int which = blockIdx.y;
    const float* W = (which == 0) ? Wq : ((which == 1) ? Wk : Wv);
    int m0 = blockIdx.x * 128;
    int tid = threadIdx.x;
    int w = tid >> 5, lane = tid & 31, g = lane >> 2, t = lane & 3;
    int wm = w >> 1, wn = w & 1;

    float acc[2][4][4];
#pragma unroll
    for (int mi = 0; mi < 2; mi++)
#pragma unroll
        for (int ni = 0; ni < 4; ni++)
#pragma unroll
            for (int j = 0; j < 4; j++) acc[mi][ni][j] = 0.f;

    for (int k0 = 0; k0 < EMB; k0 += 32) {
#pragma unroll
        for (int i = 0; i < 4; i++) {                // x tile 128x32
            int lin = tid + i * 256;
            int row = lin >> 3, c4 = lin & 7;
            float4 v = *(const float4*)&x[(size_t)(m0 + row) * EMB + k0 + c4 * 4];
            v.x = cvt_tf32(v.x); v.y = cvt_tf32(v.y);
            v.z = cvt_tf32(v.z); v.w = cvt_tf32(v.w);
            *(float4*)&xs[row * 36 + c4 * 4] = v;
        }
#pragma unroll
        for (int i = 0; i < 2; i++) {                // W tile 64x32
            int lin = tid + i * 256;
            int row = lin >> 3, c4 = lin & 7;
            float4 v = *(const float4*)&W[(size_t)row * EMB + k0 + c4 * 4];
            v.x = cvt_tf32(v.x); v.y = cvt_tf32(v.y);
            v.z = cvt_tf32(v.z); v.w = cvt_tf32(v.w);
            *(float4*)&ws[row * 36 + c4 * 4] = v;
        }
        __syncthreads();
#pragma unroll
        for (int k8 = 0; k8 < 4; k8++) {
            float a[2][4];
#pragma unroll
            for (int mi = 0; mi < 2; mi++) {
                int r = wm * 32 + mi * 16 + g;
                a[mi][0] = xs[r * 36 + k8 * 8 + t];
                a[mi][1] = xs[(r + 8) * 36 + k8 * 8 + t];
                a[mi][2] = xs[r * 36 + k8 * 8 + t + 4];
                a[mi][3] = xs[(r + 8) * 36 + k8 * 8 + t + 4];
            }
#pragma unroll
            for (int ni = 0; ni < 4; ni++) {
                int d = wn * 32 + ni * 8 + g;
                float b0 = ws[d * 36 + k8 * 8 + t];
                float b1 = ws[d * 36 + k8 * 8 + t + 4];
                mma_tf32(acc[0][ni], a[0], b0, b1);
                mma_tf32(acc[1][ni], a[1], b0, b1);
            }
        }
        __syncthreads();
    }

    if (which < 2) {
        float s = (which == 0) ? 0.18033688011112042f : 1.0f;  // 0.125*log2(e)
        float* O = (which == 0) ? g_Q : g_K;
#pragma unroll
        for (int mi = 0; mi < 2; mi++)
#pragma unroll
            for (int ni = 0; ni < 4; ni++) {
                int r = m0 + wm * 32 + mi * 16 + g;
                int c = wn * 32 + ni * 8 + 2 * t;
                float2 v0 = make_float2(cvt_tf32(acc[mi][ni][0] * s), cvt_tf32(acc[mi][ni][1] * s));
                float2 v1 = make_float2(cvt_tf32(acc[mi][ni][2] * s), cvt_tf32(acc[mi][ni][3] * s));
                *(float2*)&O[(size_t)r * HD + c] = v0;
                *(float2*)&O[(size_t)(r + 8) * HD + c] = v1;
            }
    } else {
        __half* hs = (__half*)xs;                    // [64 d][136 s-pad]
#pragma unroll
        for (int mi = 0; mi < 2; mi++)
#pragma unroll
            for (int ni = 0; ni < 4; ni++) {
                int rl = wm * 32 + mi * 16 + g;
                int c = wn * 32 + ni * 8 + 2 * t;
                hs[c * 136 + rl]           = __float2half_rn(acc[mi][ni][0]);
                hs[(c + 1) * 136 + rl]     = __float2half_rn(acc[mi][ni][1]);
                hs[c * 136 + rl + 8]       = __float2half_rn(acc[mi][ni][2]);
                hs[(c + 1) * 136 + rl + 8] = __float2half_rn(acc[mi][ni][3]);
            }
        __syncthreads();
        int b = m0 >> 12, s0 = m0 & (SEQ - 1);
#pragma unroll
        for (int i = 0; i < 4; i++) {
            int u = tid + i * 256;                   // 0..1023
            int d = u >> 4, c = u & 15;
            uint4 v = *(const uint4*)&hs[d * 136 + c * 8];
            *(uint4*)&g_Vh[((size_t)(b * HD + d)) * SEQ + s0 + c * 8] = v;
        }
    }
}

// ---------------------------------------------------------------------------
// Tensor-core split-K flash attention. Block = 4 warps = 64 q-rows; each warp
// owns 16 rows. Key tiles of 64. Scores: tf32 mma; P stays in registers and
// feeds fp16 m16n8k16 mma against V[d][s] smem tile. No-running-max softmax.
// ---------------------------------------------------------------------------
__global__ __launch_bounds__(128) void attn_kernel()
{
    __shared__ __align__(16) float  qs[64 * 68];
    __shared__ __align__(16) float  ks[64 * 68];
    __shared__ __align__(16) __half vs[64 * 72];

    int qt = blockIdx.x, b = blockIdx.y, seg = blockIdx.z;
    int q0 = qt * 64, k0 = seg * CH;
    if (k0 >= q0 + 64) return;
    int kend = min(k0 + CH, q0 + 64);
    int nt = (kend - k0 + 63) >> 6;

    int tid = threadIdx.x, w = tid >> 5, lane = tid & 31, g = lane >> 2, t = lane & 3;
    const size_t base = (size_t)b * SEQ * HD;

#pragma unroll
    for (int i = 0; i < 8; i++) {                    // Q tile 64x64
        int lin = tid + i * 128;
        int row = lin >> 4, c4 = lin & 15;
        *(float4*)&qs[row * 68 + c4 * 4] = *(const float4*)&g_Q[base + (size_t)(q0 + row) * HD + c4 * 4];
    }
    __syncthreads();

    float qa[8][4];
#pragma unroll
    for (int k8 = 0; k8 < 8; k8++) {
        int r = w * 16 + g;
        qa[k8][0] = qs[r * 68 + k8 * 8 + t];
        qa[k8][1] = qs[(r + 8) * 68 + k8 * 8 + t];
        qa[k8][2] = qs[r * 68 + k8 * 8 + t + 4];
        qa[k8][3] = qs[(r + 8) * 68 + k8 * 8 + t + 4];
    }

    float oacc[8][4];
#pragma unroll
    for (int nd = 0; nd < 8; nd++)
#pragma unroll
        for (int j = 0; j < 4; j++) oacc[nd][j] = 0.f;
    float l0 = 0.f, l1 = 0.f;
    int r0 = q0 + w * 16 + g, r1 = r0 + 8;

    for (int kt = 0; kt < nt; kt++) {
        int kb = k0 + kt * 64;
        __syncthreads();
#pragma unroll
        for (int i = 0; i < 8; i++) {                // K tile 64x64 f32
            int lin = tid + i * 128;
            int row = lin >> 4, c4 = lin & 15;
            *(float4*)&ks[row * 68 + c4 * 4] =
                *(const float4*)&g_K[base + (size_t)(kb + row) * HD + c4 * 4];
        }
#pragma unroll
        for (int i = 0; i < 4; i++) {                // V tile 64d x 64s fp16
            int lin = tid + i * 128;
            int d = lin >> 3, c = lin & 7;
            *(uint4*)&vs[d * 72 + c * 8] =
                *(const uint4*)&g_Vh[((size_t)(b * HD + d)) * SEQ + kb + c * 8];
        }
        __syncthreads();

        float sacc[8][4];
#pragma unroll
        for (int n8 = 0; n8 < 8; n8++)
#pragma unroll
            for (int j = 0; j < 4; j++) sacc[n8][j] = 0.f;
#pragma unroll
        for (int k8 = 0; k8 < 8; k8++)
#pragma unroll
            for (int n8 = 0; n8 < 8; n8++) {
                float b0 = ks[(n8 * 8 + g) * 68 + k8 * 8 + t];
                float b1 = ks[(n8 * 8 + g) * 68 + k8 * 8 + t + 4];
                mma_tf32(sacc[n8], qa[k8], b0, b1);
            }

        uint32_t ph[8][2];
#pragma unroll
        for (int n8 = 0; n8 < 8; n8++) {
            int c = kb + n8 * 8 + 2 * t;
            float p0 = (c     <= r0) ? ex2(sacc[n8][0]) : 0.f;
            float p1 = (c + 1 <= r0) ? ex2(sacc[n8][1]) : 0.f;
            float p2 = (c     <= r1) ? ex2(sacc[n8][2]) : 0.f;
            float p3 = (c + 1 <= r1) ? ex2(sacc[n8][3]) : 0.f;
            l0 += p0 + p1; l1 += p2 + p3;
            __half2 h0 = __floats2half2_rn(p0, p1);
            __half2 h1 = __floats2half2_rn(p2, p3);
            ph[n8][0] = *(uint32_t*)&h0;
            ph[n8][1] = *(uint32_t*)&h1;
        }

#pragma unroll
        for (int kt2 = 0; kt2 < 4; kt2++) {
            uint32_t a0 = ph[2 * kt2][0], a1 = ph[2 * kt2][1];
            uint32_t a2 = ph[2 * kt2 + 1][0], a3 = ph[2 * kt2 + 1][1];
#pragma unroll
            for (int nd = 0; nd < 8; nd++) {
                uint32_t b0 = *(const uint32_t*)&vs[(nd * 8 + g) * 72 + 16 * kt2 + 2 * t];
                uint32_t b1 = *(const uint32_t*)&vs[(nd * 8 + g) * 72 + 16 * kt2 + 2 * t + 8];
                mma_f16(oacc[nd], a0, a1, a2, a3, b0, b1);
            }
        }
    }

    float* po = &g_pO[(size_t)(b * NSEG + seg) * SEQ * HD];
#pragma unroll
    for (int nd = 0; nd < 8; nd++) {
        int d = nd * 8 + 2 * t;
        *(float2*)&po[(size_t)r0 * HD + d] = make_float2(oacc[nd][0], oacc[nd][1]);
        *(float2*)&po[(size_t)r1 * HD + d] = make_float2(oacc[nd][2], oacc[nd][3]);
    }
    l0 += __shfl_xor_sync(0xffffffffu, l0, 1);
    l0 += __shfl_xor_sync(0xffffffffu, l0, 2);
    l1 += __shfl_xor_sync(0xffffffffu, l1, 1);
    l1 += __shfl_xor_sync(0xffffffffu, l1, 2);
    if (t == 0) {
        g_pL[(size_t)(b * NSEG + seg) * SEQ + r0] = l0;
        g_pL[(size_t)(b * NSEG + seg) * SEQ + r1] = l1;
    }
}

// ---------------------------------------------------------------------------
__global__ __launch_bounds__(256) void reduce_kernel(float* __restrict__ out)
{
    int idx = blockIdx.x * 256 + threadIdx.x;
    if (idx >= BATCH * SEQ * HD) return;
    int d   = idx & (HD - 1);
    int row = (idx >> 6) & (SEQ - 1);
    int b   = idx >> 18;
    int ns  = (row / CH) + 1;

    float so = 0.f, sl = 0.f;
    for (int s = 0; s < ns; s++) {
        so += g_pO[((size_t)(b * NSEG + s) * SEQ + row) * HD + d];
        sl += g_pL[(size_t)(b * NSEG + s) * SEQ + row];
    }
    out[idx] = so / sl;
}

// ---------------------------------------------------------------------------
extern "C" void kernel_launch(void* const* d_in, const int* in_sizes, int n_in,
                              void* d_out, int out_size)
{
    const float* x  = (const float*)d_in[0];
    const float* Wq = (const float*)d_in[1];
    const float* Wk = (const float*)d_in[2];
    const float* Wv = (const float*)d_in[3];
    float* out = (float*)d_out;

    qkv_kernel<<<dim3(BATCH * SEQ / 128, 3), 256>>>(x, Wq, Wk, Wv);
    attn_kernel<<<dim3(SEQ / 64, BATCH, NSEG), 128>>>();
    reduce_kernel<<<(BATCH * SEQ * HD + 255) / 256, 256>>>(out);
}

// round 4
// speedup vs baseline: 5.1149x; 1.3387x over previous
#include <cuda_runtime.h>
#include <cuda_fp16.h>
#include <cstdint>

#define BATCH 4
#define SEQ   4096
#define EMB   1024
#define HD    64
#define NSEG  4
#define CH    1024

__device__ __half g_Qh[BATCH * SEQ * HD];     // fp16, pre-scaled 0.125*log2e
__device__ __half g_Kh[BATCH * SEQ * HD];     // fp16
__device__ __half g_Vh[BATCH * HD * SEQ];     // V transposed [b][d][s], fp16
__device__ float  g_pO[BATCH * NSEG * SEQ * HD];
__device__ float  g_pL[BATCH * NSEG * SEQ];

__device__ __forceinline__ float ex2(float x) {
    float r; asm("ex2.approx.f32 %0, %1;" : "=f"(r) : "f"(x)); return r;
}
__device__ __forceinline__ void mma_f16(float (&c)[4], uint32_t a0, uint32_t a1,
                                        uint32_t a2, uint32_t a3, uint32_t b0, uint32_t b1) {
    asm volatile(
        "mma.sync.aligned.m16n8k16.row.col.f32.f16.f16.f32 "
        "{%0,%1,%2,%3}, {%4,%5,%6,%7}, {%8,%9}, {%0,%1,%2,%3};"
        : "+f"(c[0]), "+f"(c[1]), "+f"(c[2]), "+f"(c[3])
        : "r"(a0), "r"(a1), "r"(a2), "r"(a3), "r"(b0), "r"(b1));
}
__device__ __forceinline__ void cp16(uint32_t s_addr, const void* g_ptr) {
    asm volatile("cp.async.cg.shared.global [%0], [%1], 16;\n" :: "r"(s_addr), "l"(g_ptr));
}

// ---------------------------------------------------------------------------
// QKV: fp16 mma, BM=128 BN=64 BK=32, 256 thr (8 warps = 4m x 2n), register
// prefetch + double-buffered smem. which: 0=Q(scaled) 1=K 2=V(transposed).
// ---------------------------------------------------------------------------
__global__ __launch_bounds__(256, 2) void qkv_kernel(
    const float* __restrict__ x, const float* __restrict__ Wq,
    const float* __restrict__ Wk, const float* __restrict__ Wv)
{
    __shared__ __align__(16) __half xs[2][128 * 40];
    __shared__ __align__(16) __half ws[2][64 * 40];

    int which = blockIdx.y;
    const float* W = (which == 0) ? Wq : ((which == 1) ? Wk : Wv);
    int m0 = blockIdx.x * 128;
    int tid = threadIdx.x;
    int w = tid >> 5, lane = tid & 31, g = lane >> 2, t = lane & 3;
    int wm = w >> 1, wn = w & 1;

    int xrow = tid >> 3, xc4 = tid & 7;          // loader coords

    float acc[2][4][4];
#pragma unroll
    for (int mi = 0; mi < 2; mi++)
#pragma unroll
        for (int ni = 0; ni < 4; ni++)
#pragma unroll
            for (int j = 0; j < 4; j++) acc[mi][ni][j] = 0.f;

    // iter 0 direct load
    {
#pragma unroll
        for (int i = 0; i < 4; i++) {            // x: 128x32 f32 -> fp16
            int row = xrow + i * 32;
            float4 v = *(const float4*)&x[(size_t)(m0 + row) * EMB + xc4 * 4];
            __half2 h0 = __floats2half2_rn(v.x, v.y), h1 = __floats2half2_rn(v.z, v.w);
            uint2 u = make_uint2(*(uint32_t*)&h0, *(uint32_t*)&h1);
            *(uint2*)&xs[0][row * 40 + xc4 * 4] = u;
        }
#pragma unroll
        for (int i = 0; i < 2; i++) {            // W: 64x32
            int row = xrow + i * 32;
            float4 v = *(const float4*)&W[(size_t)row * EMB + xc4 * 4];
            __half2 h0 = __floats2half2_rn(v.x, v.y), h1 = __floats2half2_rn(v.z, v.w);
            uint2 u = make_uint2(*(uint32_t*)&h0, *(uint32_t*)&h1);
            *(uint2*)&ws[0][row * 40 + xc4 * 4] = u;
        }
    }
    __syncthreads();

    const int NIT = EMB / 32;
    for (int it = 0; it < NIT; it++) {
        float4 px[4], pw[2];
        if (it + 1 < NIT) {
            int k0 = (it + 1) * 32;
#pragma unroll
            for (int i = 0; i < 4; i++)
                px[i] = *(const float4*)&x[(size_t)(m0 + xrow + i * 32) * EMB + k0 + xc4 * 4];
#pragma unroll
            for (int i = 0; i < 2; i++)
                pw[i] = *(const float4*)&W[(size_t)(xrow + i * 32) * EMB + k0 + xc4 * 4];
        }

        const __half* xb = xs[it & 1];
        const __half* wb = ws[it & 1];
#pragma unroll
        for (int c = 0; c < 2; c++) {            // two k16 chunks
            uint32_t a[2][4];
#pragma unroll
            for (int mi = 0; mi < 2; mi++) {
                int r = wm * 32 + mi * 16 + g;
                a[mi][0] = *(const uint32_t*)&xb[r * 40 + 2 * t + 16 * c];
                a[mi][1] = *(const uint32_t*)&xb[(r + 8) * 40 + 2 * t + 16 * c];
                a[mi][2] = *(const uint32_t*)&xb[r * 40 + 2 * t + 8 + 16 * c];
                a[mi][3] = *(const uint32_t*)&xb[(r + 8) * 40 + 2 * t + 8 + 16 * c];
            }
#pragma unroll
            for (int ni = 0; ni < 4; ni++) {
                int d = wn * 32 + ni * 8 + g;
                uint32_t b0 = *(const uint32_t*)&wb[d * 40 + 2 * t + 16 * c];
                uint32_t b1 = *(const uint32_t*)&wb[d * 40 + 2 * t + 8 + 16 * c];
                mma_f16(acc[0][ni], a[0][0], a[0][1], a[0][2], a[0][3], b0, b1);
                mma_f16(acc[1][ni], a[1][0], a[1][1], a[1][2], a[1][3], b0, b1);
            }
        }

        if (it + 1 < NIT) {
            __half* xn = xs[(it + 1) & 1];
            __half* wn2 = ws[(it + 1) & 1];
#pragma unroll
            for (int i = 0; i < 4; i++) {
                __half2 h0 = __floats2half2_rn(px[i].x, px[i].y);
                __half2 h1 = __floats2half2_rn(px[i].z, px[i].w);
                uint2 u = make_uint2(*(uint32_t*)&h0, *(uint32_t*)&h1);
                *(uint2*)&xn[(xrow + i * 32) * 40 + xc4 * 4] = u;
            }
#pragma unroll
            for (int i = 0; i < 2; i++) {
                __half2 h0 = __floats2half2_rn(pw[i].x, pw[i].y);
                __half2 h1 = __floats2half2_rn(pw[i].z, pw[i].w);
                uint2 u = make_uint2(*(uint32_t*)&h0, *(uint32_t*)&h1);
                *(uint2*)&wn2[(xrow + i * 32) * 40 + xc4 * 4] = u;
            }
        }
        __syncthreads();
    }

    if (which < 2) {
        float s = (which == 0) ? 0.18033688011112042f : 1.0f;  // 0.125*log2(e)
        __half* O = (which == 0) ? g_Qh : g_Kh;
#pragma unroll
        for (int mi = 0; mi < 2; mi++)
#pragma unroll
            for (int ni = 0; ni < 4; ni++) {
                int r = m0 + wm * 32 + mi * 16 + g;
                int c = wn * 32 + ni * 8 + 2 * t;
                __half2 h0 = __floats2half2_rn(acc[mi][ni][0] * s, acc[mi][ni][1] * s);
                __half2 h1 = __floats2half2_rn(acc[mi][ni][2] * s, acc[mi][ni][3] * s);
                *(uint32_t*)&O[(size_t)r * HD + c] = *(uint32_t*)&h0;
                *(uint32_t*)&O[(size_t)(r + 8) * HD + c] = *(uint32_t*)&h1;
            }
    } else {
        __half* hs = (__half*)xs;                // [64 d][136 s-pad]
#pragma unroll
        for (int mi = 0; mi < 2; mi++)
#pragma unroll
            for (int ni = 0; ni < 4; ni++) {
                int rl = wm * 32 + mi * 16 + g;
                int c = wn * 32 + ni * 8 + 2 * t;
                hs[c * 136 + rl]           = __float2half_rn(acc[mi][ni][0]);
                hs[(c + 1) * 136 + rl]     = __float2half_rn(acc[mi][ni][1]);
                hs[c * 136 + rl + 8]       = __float2half_rn(acc[mi][ni][2]);
                hs[(c + 1) * 136 + rl + 8] = __float2half_rn(acc[mi][ni][3]);
            }
        __syncthreads();
        int b = m0 >> 12, s0 = m0 & (SEQ - 1);
#pragma unroll
        for (int i = 0; i < 4; i++) {
            int u = tid + i * 256;
            int d = u >> 4, c = u & 15;
            uint4 v = *(const uint4*)&hs[d * 136 + c * 8];
            *(uint4*)&g_Vh[((size_t)(b * HD + d)) * SEQ + s0 + c * 8] = v;
        }
    }
}

// ---------------------------------------------------------------------------
// fp16 tensor-core split-K flash attention with cp.async double buffering.
// Block = 4 warps = 64 q rows; k tiles of 64.
// ---------------------------------------------------------------------------
__global__ __launch_bounds__(128) void attn_kernel()
{
    __shared__ __align__(16) __half qs[64 * 72];
    __shared__ __align__(16) __half ks[2][64 * 72];
    __shared__ __align__(16) __half vs[2][64 * 72];

    int qt = blockIdx.x, b = blockIdx.y, seg = blockIdx.z;
    int q0 = qt * 64, k0 = seg * CH;
    if (k0 >= q0 + 64) return;
    int kend = min(k0 + CH, q0 + 64);
    int nt = (kend - k0 + 63) >> 6;

    int tid = threadIdx.x, w = tid >> 5, lane = tid & 31, g = lane >> 2, t = lane & 3;
    const size_t base = (size_t)b * SEQ * HD;
    int lrow = tid >> 3, lc8 = tid & 7;          // loader coords (16B units)

    // Q tile + fragments
#pragma unroll
    for (int i = 0; i < 4; i++) {
        int row = lrow + i * 16;
        *(uint4*)&qs[row * 72 + lc8 * 8] =
            *(const uint4*)&g_Qh[base + (size_t)(q0 + row) * HD + lc8 * 8];
    }
    __syncthreads();
    uint32_t qa[4][4];
    {
        int r = w * 16 + g;
#pragma unroll
        for (int c = 0; c < 4; c++) {
            qa[c][0] = *(const uint32_t*)&qs[r * 72 + 2 * t + 16 * c];
            qa[c][1] = *(const uint32_t*)&qs[(r + 8) * 72 + 2 * t + 16 * c];
            qa[c][2] = *(const uint32_t*)&qs[r * 72 + 2 * t + 8 + 16 * c];
            qa[c][3] = *(const uint32_t*)&qs[(r + 8) * 72 + 2 * t + 8 + 16 * c];
        }
    }

    float oacc[8][4];
#pragma unroll
    for (int nd = 0; nd < 8; nd++)
#pragma unroll
        for (int j = 0; j < 4; j++) oacc[nd][j] = 0.f;
    float l0 = 0.f, l1 = 0.f;
    int r0 = q0 + w * 16 + g, r1 = r0 + 8;

    // cp.async issue helper (tile kb -> buffer bf)
    auto issue = [&](int kb, int bf) {
#pragma unroll
        for (int i = 0; i < 4; i++) {
            int row = lrow + i * 16;
            cp16((uint32_t)__cvta_generic_to_shared(&ks[bf][row * 72 + lc8 * 8]),
                 &g_Kh[base + (size_t)(kb + row) * HD + lc8 * 8]);
            cp16((uint32_t)__cvta_generic_to_shared(&vs[bf][row * 72 + lc8 * 8]),
                 &g_Vh[((size_t)(b * HD + row)) * SEQ + kb + lc8 * 8]);
        }
        asm volatile("cp.async.commit_group;\n" ::: "memory");
    };

    issue(k0, 0);
    for (int kt = 0; kt < nt; kt++) {
        int kb = k0 + kt * 64;
        if (kt + 1 < nt) {
            issue(kb + 64, (kt + 1) & 1);
            asm volatile("cp.async.wait_group 1;\n" ::: "memory");
        } else {
            asm volatile("cp.async.wait_group 0;\n" ::: "memory");
        }
        __syncthreads();

        const __half* kbuf = ks[kt & 1];
        const __half* vbuf = vs[kt & 1];

        float sacc[8][4];
#pragma unroll
        for (int n8 = 0; n8 < 8; n8++)
#pragma unroll
            for (int j = 0; j < 4; j++) sacc[n8][j] = 0.f;
#pragma unroll
        for (int c = 0; c < 4; c++)
#pragma unroll
            for (int n8 = 0; n8 < 8; n8++) {
                uint32_t b0 = *(const uint32_t*)&kbuf[(n8 * 8 + g) * 72 + 2 * t + 16 * c];
                uint32_t b1 = *(const uint32_t*)&kbuf[(n8 * 8 + g) * 72 + 2 * t + 8 + 16 * c];
                mma_f16(sacc[n8], qa[c][0], qa[c][1], qa[c][2], qa[c][3], b0, b1);
            }

        uint32_t ph[8][2];
#pragma unroll
        for (int n8 = 0; n8 < 8; n8++) {
            int c = kb + n8 * 8 + 2 * t;
            float p0 = (c     <= r0) ? ex2(sacc[n8][0]) : 0.f;
            float p1 = (c + 1 <= r0) ? ex2(sacc[n8][1]) : 0.f;
            float p2 = (c     <= r1) ? ex2(sacc[n8][2]) : 0.f;
            float p3 = (c + 1 <= r1) ? ex2(sacc[n8][3]) : 0.f;
            l0 += p0 + p1; l1 += p2 + p3;
            __half2 h0 = __floats2half2_rn(p0, p1);
            __half2 h1 = __floats2half2_rn(p2, p3);
            ph[n8][0] = *(uint32_t*)&h0;
            ph[n8][1] = *(uint32_t*)&h1;
        }

#pragma unroll
        for (int c2 = 0; c2 < 4; c2++) {
            uint32_t a0 = ph[2 * c2][0], a1 = ph[2 * c2][1];
            uint32_t a2 = ph[2 * c2 + 1][0], a3 = ph[2 * c2 + 1][1];
#pragma unroll
            for (int nd = 0; nd < 8; nd++) {
                uint32_t b0 = *(const uint32_t*)&vbuf[(nd * 8 + g) * 72 + 16 * c2 + 2 * t];
                uint32_t b1 = *(const uint32_t*)&vbuf[(nd * 8 + g) * 72 + 16 * c2 + 2 * t + 8];
                mma_f16(oacc[nd], a0, a1, a2, a3, b0, b1);
            }
        }
        __syncthreads();
    }

    float* po = &g_pO[(size_t)(b * NSEG + seg) * SEQ * HD];
#pragma unroll
    for (int nd = 0; nd < 8; nd++) {
        int d = nd * 8 + 2 * t;
        *(float2*)&po[(size_t)r0 * HD + d] = make_float2(oacc[nd][0], oacc[nd][1]);
        *(float2*)&po[(size_t)r1 * HD + d] = make_float2(oacc[nd][2], oacc[nd][3]);
    }
    l0 += __shfl_xor_sync(0xffffffffu, l0, 1);
    l0 += __shfl_xor_sync(0xffffffffu, l0, 2);
    l1 += __shfl_xor_sync(0xffffffffu, l1, 1);
    l1 += __shfl_xor_sync(0xffffffffu, l1, 2);
    if (t == 0) {
        g_pL[(size_t)(b * NSEG + seg) * SEQ + r0] = l0;
        g_pL[(size_t)(b * NSEG + seg) * SEQ + r1] = l1;
    }
}

// ---------------------------------------------------------------------------
__global__ __launch_bounds__(256) void reduce_kernel(float* __restrict__ out)
{
    int idx = blockIdx.x * 256 + threadIdx.x;
    if (idx >= BATCH * SEQ * HD) return;
    int d   = idx & (HD - 1);
    int row = (idx >> 6) & (SEQ - 1);
    int b   = idx >> 18;
    int ns  = (row / CH) + 1;

    float so = 0.f, sl = 0.f;
    for (int s = 0; s < ns; s++) {
        so += g_pO[((size_t)(b * NSEG + s) * SEQ + row) * HD + d];
        sl += g_pL[(size_t)(b * NSEG + s) * SEQ + row];
    }
    out[idx] = so / sl;
}

// ---------------------------------------------------------------------------
extern "C" void kernel_launch(void* const* d_in, const int* in_sizes, int n_in,
                              void* d_out, int out_size)
{
    const float* x  = (const float*)d_in[0];
    const float* Wq = (const float*)d_in[1];
    const float* Wk = (const float*)d_in[2];
    const float* Wv = (const float*)d_in[3];
    float* out = (float*)d_out;

    qkv_kernel<<<dim3(BATCH * SEQ / 128, 3), 256>>>(x, Wq, Wk, Wv);
    attn_kernel<<<dim3(SEQ / 64, BATCH, NSEG), 128>>>();
    reduce_kernel<<<(BATCH * SEQ * HD + 255) / 256, 256>>>(out);
}

// round 7
// speedup vs baseline: 6.4578x; 1.2626x over previous
#include <cuda_runtime.h>
#include <cuda_fp16.h>
#include <cstdint>

#define BATCH 4
#define SEQ   4096
#define EMB   1024
#define HD    64
#define NSEG  4
#define CH    1024

__device__ __half g_Qh[BATCH * SEQ * HD];     // fp16, pre-scaled 0.125*log2e
__device__ __half g_Kh[BATCH * SEQ * HD];     // fp16
__device__ __half g_Vh[BATCH * HD * SEQ];     // V transposed [b][d][s], fp16
__device__ float  g_pO[BATCH * NSEG * SEQ * HD];
__device__ float  g_pL[BATCH * NSEG * SEQ];

__device__ __forceinline__ float ex2(float x) {
    float r; asm("ex2.approx.f32 %0, %1;" : "=f"(r) : "f"(x)); return r;
}
__device__ __forceinline__ void mma_f16(float (&c)[4], uint32_t a0, uint32_t a1,
                                        uint32_t a2, uint32_t a3, uint32_t b0, uint32_t b1) {
    asm volatile(
        "mma.sync.aligned.m16n8k16.row.col.f32.f16.f16.f32 "
        "{%0,%1,%2,%3}, {%4,%5,%6,%7}, {%8,%9}, {%0,%1,%2,%3};"
        : "+f"(c[0]), "+f"(c[1]), "+f"(c[2]), "+f"(c[3])
        : "r"(a0), "r"(a1), "r"(a2), "r"(a3), "r"(b0), "r"(b1));
}
__device__ __forceinline__ void cp16(uint32_t s_addr, const void* g_ptr) {
    asm volatile("cp.async.cg.shared.global [%0], [%1], 16;\n" :: "r"(s_addr), "l"(g_ptr));
}
__device__ __forceinline__ uint32_t pack2(float a, float b) {
    __half2 h = __floats2half2_rn(a, b);
    return *(uint32_t*)&h;
}

// ---------------------------------------------------------------------------
// Fused QKV GEMM: one pass over x computes Q|K|V (stacked N=192).
// BM=128, BN=192, BK=32. 256 thr = 8 warps (2m x 4n). Warp tile 64m x 48n,
// with n8 tiles interleaved (gcol = (wn + 4*ni)*8) so each tile is purely
// Q, K, or V. cp.async fp32 double buffer; fp32->fp16 at fragment load.
// ---------------------------------------------------------------------------
#define XS_STRIDE 40
#define XS_BUF    (128 * XS_STRIDE)
#define WS_BUF    (192 * XS_STRIDE)
#define QKV_SMEM  ((2 * XS_BUF + 2 * WS_BUF) * 4)

__global__ __launch_bounds__(256, 1) void qkv_fused_kernel(
    const float* __restrict__ x, const float* __restrict__ Wq,
    const float* __restrict__ Wk, const float* __restrict__ Wv)
{
    extern __shared__ __align__(16) float smem[];
    float* xs  = smem;                 // 2 x [128][40]
    float* wsm = smem + 2 * XS_BUF;    // 2 x [192][40]

    int m0 = blockIdx.x * 128;
    int tid = threadIdx.x;
    int w = tid >> 5, lane = tid & 31, g = lane >> 2, t = lane & 3;
    int wm = w >> 2, wn = w & 3;
    int lr = tid >> 3, lc4 = tid & 7;  // loader coords

    auto issue_tile = [&](int it, int bf) {
        int k0 = it * 32;
        float* xd = xs + bf * XS_BUF;
#pragma unroll
        for (int i = 0; i < 4; i++) {
            int row = lr + i * 32;
            cp16((uint32_t)__cvta_generic_to_shared(&xd[row * XS_STRIDE + lc4 * 4]),
                 &x[(size_t)(m0 + row) * EMB + k0 + lc4 * 4]);
        }
        float* wd = wsm + bf * WS_BUF;
#pragma unroll
        for (int i = 0; i < 6; i++) {
            int r = lr + i * 32;
            const float* wp = (r < 64) ? (Wq + (size_t)r * EMB)
                             : (r < 128) ? (Wk + (size_t)(r - 64) * EMB)
                                         : (Wv + (size_t)(r - 128) * EMB);
            cp16((uint32_t)__cvta_generic_to_shared(&wd[r * XS_STRIDE + lc4 * 4]),
                 wp + k0 + lc4 * 4);
        }
        asm volatile("cp.async.commit_group;\n" ::: "memory");
    };

    float acc[4][6][4];
#pragma unroll
    for (int mi = 0; mi < 4; mi++)
#pragma unroll
        for (int ni = 0; ni < 6; ni++)
#pragma unroll
            for (int j = 0; j < 4; j++) acc[mi][ni][j] = 0.f;

    const int NIT = EMB / 32;
    issue_tile(0, 0);

    for (int it = 0; it < NIT; it++) {
        if (it + 1 < NIT) {
            issue_tile(it + 1, (it + 1) & 1);
            asm volatile("cp.async.wait_group 1;\n" ::: "memory");
        } else {
            asm volatile("cp.async.wait_group 0;\n" ::: "memory");
        }
        __syncthreads();

        const float* xb = xs + (it & 1) * XS_BUF;
        const float* wb = wsm + (it & 1) * WS_BUF;

#pragma unroll
        for (int c = 0; c < 2; c++) {
            uint32_t a[4][4];
#pragma unroll
            for (int mi = 0; mi < 4; mi++) {
                int r = wm * 64 + mi * 16 + g;
                float2 f0 = *(const float2*)&xb[r * XS_STRIDE + 16 * c + 2 * t];
                float2 f1 = *(const float2*)&xb[(r + 8) * XS_STRIDE + 16 * c + 2 * t];
                float2 f2 = *(const float2*)&xb[r * XS_STRIDE + 16 * c + 2 * t + 8];
                float2 f3 = *(const float2*)&xb[(r + 8) * XS_STRIDE + 16 * c + 2 * t + 8];
                a[mi][0] = pack2(f0.x, f0.y);
                a[mi][1] = pack2(f1.x, f1.y);
                a[mi][2] = pack2(f2.x, f2.y);
                a[mi][3] = pack2(f3.x, f3.y);
            }
#pragma unroll
            for (int ni = 0; ni < 6; ni++) {
                int d = (wn + 4 * ni) * 8 + g;
                float2 g0 = *(const float2*)&wb[d * XS_STRIDE + 16 * c + 2 * t];
                float2 g1 = *(const float2*)&wb[d * XS_STRIDE + 16 * c + 2 * t + 8];
                uint32_t b0 = pack2(g0.x, g0.y);
                uint32_t b1 = pack2(g1.x, g1.y);
#pragma unroll
                for (int mi = 0; mi < 4; mi++)
                    mma_f16(acc[mi][ni], a[mi][0], a[mi][1], a[mi][2], a[mi][3], b0, b1);
            }
        }
        __syncthreads();
    }

    // Epilogue: Q/K direct fp16 stores; V transposed through smem.
    const float SCQ = 0.18033688011112042f;       // 0.125 * log2(e)
    __half* hs = (__half*)smem;                   // [64 d][136]
#pragma unroll
    for (int mi = 0; mi < 4; mi++)
#pragma unroll
        for (int ni = 0; ni < 6; ni++) {
            int gcol = (wn + 4 * ni) * 8 + 2 * t;
            int r = m0 + wm * 64 + mi * 16 + g;
            if (gcol < 64) {
                *(uint32_t*)&g_Qh[(size_t)r * HD + gcol] =
                    pack2(acc[mi][ni][0] * SCQ, acc[mi][ni][1] * SCQ);
                *(uint32_t*)&g_Qh[(size_t)(r + 8) * HD + gcol] =
                    pack2(acc[mi][ni][2] * SCQ, acc[mi][ni][3] * SCQ);
            } else if (gcol < 128) {
                *(uint32_t*)&g_Kh[(size_t)r * HD + gcol - 64] =
                    pack2(acc[mi][ni][0], acc[mi][ni][1]);
                *(uint32_t*)&g_Kh[(size_t)(r + 8) * HD + gcol - 64] =
                    pack2(acc[mi][ni][2], acc[mi][ni][3]);
            }
        }
    __syncthreads();                              // smem reuse for V transpose
#pragma unroll
    for (int mi = 0; mi < 4; mi++)
#pragma unroll
        for (int ni = 4; ni < 6; ni++) {
            int gcol = (wn + 4 * ni) * 8 + 2 * t;
            int d = gcol - 128;
            int rl = wm * 64 + mi * 16 + g;
            hs[d * 136 + rl]           = __float2half_rn(acc[mi][ni][0]);
            hs[(d + 1) * 136 + rl]     = __float2half_rn(acc[mi][ni][1]);
            hs[d * 136 + rl + 8]       = __float2half_rn(acc[mi][ni][2]);
            hs[(d + 1) * 136 + rl + 8] = __float2half_rn(acc[mi][ni][3]);
        }
    __syncthreads();
    int b = m0 >> 12, s0 = m0 & (SEQ - 1);
#pragma unroll
    for (int i = 0; i < 4; i++) {
        int u = tid + i * 256;                    // 1024 uint4 = 64d x 16
        int d = u >> 4, c = u & 15;
        uint4 v = *(const uint4*)&hs[d * 136 + c * 8];
        *(uint4*)&g_Vh[((size_t)(b * HD + d)) * SEQ + s0 + c * 8] = v;
    }
}

// ---------------------------------------------------------------------------
// fp16 tensor-core split-K flash attention with cp.async double buffering.
// Block = 4 warps = 64 q rows; k tiles of 64. (unchanged from round 4)
// ---------------------------------------------------------------------------
__global__ __launch_bounds__(128) void attn_kernel()
{
    __shared__ __align__(16) __half qs[64 * 72];
    __shared__ __align__(16) __half ks[2][64 * 72];
    __shared__ __align__(16) __half vs[2][64 * 72];

    int qt = blockIdx.x, b = blockIdx.y, seg = blockIdx.z;
    int q0 = qt * 64, k0 = seg * CH;
    if (k0 >= q0 + 64) return;
    int kend = min(k0 + CH, q0 + 64);
    int nt = (kend - k0 + 63) >> 6;

    int tid = threadIdx.x, w = tid >> 5, lane = tid & 31, g = lane >> 2, t = lane & 3;
    const size_t base = (size_t)b * SEQ * HD;
    int lrow = tid >> 3, lc8 = tid & 7;

#pragma unroll
    for (int i = 0; i < 4; i++) {
        int row = lrow + i * 16;
        *(uint4*)&qs[row * 72 + lc8 * 8] =
            *(const uint4*)&g_Qh[base + (size_t)(q0 + row) * HD + lc8 * 8];
    }
    __syncthreads();
    uint32_t qa[4][4];
    {
        int r = w * 16 + g;
#pragma unroll
        for (int c = 0; c < 4; c++) {
            qa[c][0] = *(const uint32_t*)&qs[r * 72 + 2 * t + 16 * c];
            qa[c][1] = *(const uint32_t*)&qs[(r + 8) * 72 + 2 * t + 16 * c];
            qa[c][2] = *(const uint32_t*)&qs[r * 72 + 2 * t + 8 + 16 * c];
            qa[c][3] = *(const uint32_t*)&qs[(r + 8) * 72 + 2 * t + 8 + 16 * c];
        }
    }

    float oacc[8][4];
#pragma unroll
    for (int nd = 0; nd < 8; nd++)
#pragma unroll
        for (int j = 0; j < 4; j++) oacc[nd][j] = 0.f;
    float l0 = 0.f, l1 = 0.f;
    int r0 = q0 + w * 16 + g, r1 = r0 + 8;

    auto issue = [&](int kb, int bf) {
#pragma unroll
        for (int i = 0; i < 4; i++) {
            int row = lrow + i * 16;
            cp16((uint32_t)__cvta_generic_to_shared(&ks[bf][row * 72 + lc8 * 8]),
                 &g_Kh[base + (size_t)(kb + row) * HD + lc8 * 8]);
            cp16((uint32_t)__cvta_generic_to_shared(&vs[bf][row * 72 + lc8 * 8]),
                 &g_Vh[((size_t)(b * HD + row)) * SEQ + kb + lc8 * 8]);
        }
        asm volatile("cp.async.commit_group;\n" ::: "memory");
    };

    issue(k0, 0);
    for (int kt = 0; kt < nt; kt++) {
        int kb = k0 + kt * 64;
        if (kt + 1 < nt) {
            issue(kb + 64, (kt + 1) & 1);
            asm volatile("cp.async.wait_group 1;\n" ::: "memory");
        } else {
            asm volatile("cp.async.wait_group 0;\n" ::: "memory");
        }
        __syncthreads();

        const __half* kbuf = ks[kt & 1];
        const __half* vbuf = vs[kt & 1];

        float sacc[8][4];
#pragma unroll
        for (int n8 = 0; n8 < 8; n8++)
#pragma unroll
            for (int j = 0; j < 4; j++) sacc[n8][j] = 0.f;
#pragma unroll
        for (int c = 0; c < 4; c++)
#pragma unroll
            for (int n8 = 0; n8 < 8; n8++) {
                uint32_t b0 = *(const uint32_t*)&kbuf[(n8 * 8 + g) * 72 + 2 * t + 16 * c];
                uint32_t b1 = *(const uint32_t*)&kbuf[(n8 * 8 + g) * 72 + 2 * t + 8 + 16 * c];
                mma_f16(sacc[n8], qa[c][0], qa[c][1], qa[c][2], qa[c][3], b0, b1);
            }

        uint32_t ph[8][2];
#pragma unroll
        for (int n8 = 0; n8 < 8; n8++) {
            int c = kb + n8 * 8 + 2 * t;
            float p0 = (c     <= r0) ? ex2(sacc[n8][0]) : 0.f;
            float p1 = (c + 1 <= r0) ? ex2(sacc[n8][1]) : 0.f;
            float p2 = (c     <= r1) ? ex2(sacc[n8][2]) : 0.f;
            float p3 = (c + 1 <= r1) ? ex2(sacc[n8][3]) : 0.f;
            l0 += p0 + p1; l1 += p2 + p3;
            ph[n8][0] = pack2(p0, p1);
            ph[n8][1] = pack2(p2, p3);
        }

#pragma unroll
        for (int c2 = 0; c2 < 4; c2++) {
            uint32_t a0 = ph[2 * c2][0], a1 = ph[2 * c2][1];
            uint32_t a2 = ph[2 * c2 + 1][0], a3 = ph[2 * c2 + 1][1];
#pragma unroll
            for (int nd = 0; nd < 8; nd++) {
                uint32_t b0 = *(const uint32_t*)&vbuf[(nd * 8 + g) * 72 + 16 * c2 + 2 * t];
                uint32_t b1 = *(const uint32_t*)&vbuf[(nd * 8 + g) * 72 + 16 * c2 + 2 * t + 8];
                mma_f16(oacc[nd], a0, a1, a2, a3, b0, b1);
            }
        }
        __syncthreads();
    }

    float* po = &g_pO[(size_t)(b * NSEG + seg) * SEQ * HD];
#pragma unroll
    for (int nd = 0; nd < 8; nd++) {
        int d = nd * 8 + 2 * t;
        *(float2*)&po[(size_t)r0 * HD + d] = make_float2(oacc[nd][0], oacc[nd][1]);
        *(float2*)&po[(size_t)r1 * HD + d] = make_float2(oacc[nd][2], oacc[nd][3]);
    }
    l0 += __shfl_xor_sync(0xffffffffu, l0, 1);
    l0 += __shfl_xor_sync(0xffffffffu, l0, 2);
    l1 += __shfl_xor_sync(0xffffffffu, l1, 1);
    l1 += __shfl_xor_sync(0xffffffffu, l1, 2);
    if (t == 0) {
        g_pL[(size_t)(b * NSEG + seg) * SEQ + r0] = l0;
        g_pL[(size_t)(b * NSEG + seg) * SEQ + r1] = l1;
    }
}

// ---------------------------------------------------------------------------
__global__ __launch_bounds__(256) void reduce_kernel(float* __restrict__ out)
{
    int idx = blockIdx.x * 256 + threadIdx.x;
    if (idx >= BATCH * SEQ * HD) return;
    int d   = idx & (HD - 1);
    int row = (idx >> 6) & (SEQ - 1);
    int b   = idx >> 18;
    int ns  = (row / CH) + 1;

    float so = 0.f, sl = 0.f;
    for (int s = 0; s < ns; s++) {
        so += g_pO[((size_t)(b * NSEG + s) * SEQ + row) * HD + d];
        sl += g_pL[(size_t)(b * NSEG + s) * SEQ + row];
    }
    out[idx] = so / sl;
}

// ---------------------------------------------------------------------------
extern "C" void kernel_launch(void* const* d_in, const int* in_sizes, int n_in,
                              void* d_out, int out_size)
{
    const float* x  = (const float*)d_in[0];
    const float* Wq = (const float*)d_in[1];
    const float* Wk = (const float*)d_in[2];
    const float* Wv = (const float*)d_in[3];
    float* out = (float*)d_out;

    cudaFuncSetAttribute(qkv_fused_kernel,
                         cudaFuncAttributeMaxDynamicSharedMemorySize, QKV_SMEM);
    qkv_fused_kernel<<<BATCH * SEQ / 128, 256, QKV_SMEM>>>(x, Wq, Wk, Wv);
    attn_kernel<<<dim3(SEQ / 64, BATCH, NSEG), 128>>>();
    reduce_kernel<<<(BATCH * SEQ * HD + 255) / 256, 256>>>(out);
}